// round 11
// baseline (speedup 1.0000x reference)
#include <cuda_runtime.h>
#include <cuda_fp16.h>
#include <stdint.h>

#define N_MAX 100000
#define E_MAX 6400000

// ---- scratch (device globals: no allocation allowed) ----
__device__ int      g_src[E_MAX];
__device__ int      g_dst[E_MAX];
__device__ unsigned g_deg[N_MAX];
__device__ float    g_dinv[N_MAX];
__device__ __half   g_val[N_MAX];   // per-node payload (fp16, 195KB)
__device__ float    g_agg[N_MAX];   // layer-1 aggregation (fp32 atomics)
__device__ int      g_is64;         // edge_index dtype flag (1 = int64)

// ---------------------------------------------------------------------------
// threefry2x32 — exact JAX schedule: 20 rounds = 5 blocks of 4
// ---------------------------------------------------------------------------
__host__ __device__ __forceinline__ void tf2x32(uint32_t k0, uint32_t k1,
                                                uint32_t x0, uint32_t x1,
                                                uint32_t &o0, uint32_t &o1) {
    const uint32_t ks2 = k0 ^ k1 ^ 0x1BD11BDAu;
#define TF_RND(R) { x0 += x1; x1 = (x1 << (R)) | (x1 >> (32 - (R))); x1 ^= x0; }
    x0 += k0; x1 += k1;
    TF_RND(13) TF_RND(15) TF_RND(26) TF_RND(6)
    x0 += k1;  x1 += ks2 + 1u;
    TF_RND(17) TF_RND(29) TF_RND(16) TF_RND(24)
    x0 += ks2; x1 += k0 + 2u;
    TF_RND(13) TF_RND(15) TF_RND(26) TF_RND(6)
    x0 += k0;  x1 += k1 + 3u;
    TF_RND(17) TF_RND(29) TF_RND(16) TF_RND(24)
    x0 += k1;  x1 += ks2 + 4u;
    TF_RND(13) TF_RND(15) TF_RND(26) TF_RND(6)
    x0 += ks2; x1 += k0 + 5u;
#undef TF_RND
    o0 = x0; o1 = x1;
}

__device__ __forceinline__ bool keep_bit(uint32_t ka, uint32_t kb, uint32_t idx) {
    uint32_t a, b;
    tf2x32(ka, kb, 0u, idx, a, b);
    uint32_t bits = a ^ b;
    float u = __uint_as_float((bits >> 9) | 0x3f800000u) - 1.0f;
    return u < 0.4f;
}

// ---------------------------------------------------------------------------
// kernels
// ---------------------------------------------------------------------------

// dtype detection only (zeroing moved to cudaMemsetAsync nodes)
__global__ void k_detect(const unsigned* __restrict__ e) {
    __shared__ int any32;
    if (threadIdx.x == 0) any32 = 0;
    __syncthreads();
    int local = 0;
    for (int j = threadIdx.x; j < 4096; j += blockDim.x)
        if (e[2 * j + 1] != 0u) local = 1;
    if (local) any32 = 1;
    __syncthreads();
    if (threadIdx.x == 0) g_is64 = (any32 == 0) ? 1 : 0;
}

// Convert edge_index -> int32 src/dst and count in-degree. 8 edges/thread,
// grid-stride; loads batched for MLP.
__global__ void __launch_bounds__(256) k_convert(const long long* __restrict__ e, int E) {
    int n8 = E / 8;
    int stride = gridDim.x * blockDim.x;
    int is64 = g_is64;
    for (int i = blockIdx.x * blockDim.x + threadIdx.x; i < n8; i += stride) {
        int4 sva, svb, dva, dvb;
        if (is64) {
            const longlong2* s2 = reinterpret_cast<const longlong2*>(e);
            const longlong2* d2 = reinterpret_cast<const longlong2*>(e + E);
            longlong2 sa = s2[4 * i],     sb = s2[4 * i + 1];
            longlong2 sc = s2[4 * i + 2], sd = s2[4 * i + 3];
            longlong2 da = d2[4 * i],     db = d2[4 * i + 1];
            longlong2 dc = d2[4 * i + 2], dd = d2[4 * i + 3];
            sva = make_int4((int)sa.x, (int)sa.y, (int)sb.x, (int)sb.y);
            svb = make_int4((int)sc.x, (int)sc.y, (int)sd.x, (int)sd.y);
            dva = make_int4((int)da.x, (int)da.y, (int)db.x, (int)db.y);
            dvb = make_int4((int)dc.x, (int)dc.y, (int)dd.x, (int)dd.y);
        } else {
            const int* e32 = reinterpret_cast<const int*>(e);
            sva = reinterpret_cast<const int4*>(e32)[2 * i];
            svb = reinterpret_cast<const int4*>(e32)[2 * i + 1];
            dva = reinterpret_cast<const int4*>(e32 + E)[2 * i];
            dvb = reinterpret_cast<const int4*>(e32 + E)[2 * i + 1];
        }
        reinterpret_cast<int4*>(g_src)[2 * i]     = sva;
        reinterpret_cast<int4*>(g_src)[2 * i + 1] = svb;
        reinterpret_cast<int4*>(g_dst)[2 * i]     = dva;
        reinterpret_cast<int4*>(g_dst)[2 * i + 1] = dvb;
        atomicAdd(&g_deg[dva.x], 1u);
        atomicAdd(&g_deg[dva.y], 1u);
        atomicAdd(&g_deg[dva.z], 1u);
        atomicAdd(&g_deg[dva.w], 1u);
        atomicAdd(&g_deg[dvb.x], 1u);
        atomicAdd(&g_deg[dvb.y], 1u);
        atomicAdd(&g_deg[dvb.z], 1u);
        atomicAdd(&g_deg[dvb.w], 1u);
    }
    // tail edges (E not multiple of 8)
    int tail0 = n8 * 8;
    int gid = blockIdx.x * blockDim.x + threadIdx.x;
    if (gid < E - tail0) {
        int j = tail0 + gid;
        int s, d;
        if (is64) { s = (int)e[j]; d = (int)e[E + j]; }
        else {
            const int* e32 = reinterpret_cast<const int*>(e);
            s = e32[j]; d = e32[E + j];
        }
        g_src[j] = s; g_dst[j] = d;
        atomicAdd(&g_deg[d], 1u);
    }
}

// Per-node: dinv, dropout1 on x, g1 = h1 * dinv  (stored fp16)
__global__ void k_node1(const float* __restrict__ x, int N, uint32_t ka, uint32_t kb) {
    int n = blockIdx.x * blockDim.x + threadIdx.x;
    if (n >= N) return;
    unsigned dg = g_deg[n];
    float dinv = dg ? rsqrtf((float)dg) : 0.0f;
    g_dinv[n] = dinv;
    float h = keep_bit(ka, kb, (uint32_t)n) ? x[n] * 2.5f : 0.0f;
    g_val[n] = __float2half_rn(h * dinv);
}

// Edge scatter: agg[dst] += val[src], skipping zero contributions
// (dropout makes ~60% of pass-1 values exactly zero -> no atomic needed).
// fp16 node table staged in SMEM; index loads (streaming) software-pipelined.
__global__ void __launch_bounds__(1024, 1) k_edge(float* __restrict__ agg, int n4, int N) {
    extern __shared__ __half s_val[];
    int n_u4 = (N + 7) / 8;   // uint4 = 8 halves
    const uint4* st = reinterpret_cast<const uint4*>(g_val);
    uint4* dt = reinterpret_cast<uint4*>(s_val);
    for (int j = threadIdx.x; j < n_u4; j += blockDim.x)
        dt[j] = st[j];
    __syncthreads();

    const int4* s4 = reinterpret_cast<const int4*>(g_src);
    const int4* d4 = reinterpret_cast<const int4*>(g_dst);
    int stride = gridDim.x * blockDim.x;
    int i = blockIdx.x * blockDim.x + threadIdx.x;

    int4 s, d;
    bool valid = (i < n4);
    if (valid) { s = __ldcs(&s4[i]); d = __ldcs(&d4[i]); }
    while (valid) {
        int ni = i + stride;
        bool nvalid = (ni < n4);
        int4 ns, nd;
        if (nvalid) { ns = __ldcs(&s4[ni]); nd = __ldcs(&d4[ni]); }  // prefetch
        float v0 = __half2float(s_val[s.x]);
        float v1 = __half2float(s_val[s.y]);
        float v2 = __half2float(s_val[s.z]);
        float v3 = __half2float(s_val[s.w]);
        if (v0 != 0.0f) atomicAdd(&agg[d.x], v0);
        if (v1 != 0.0f) atomicAdd(&agg[d.y], v1);
        if (v2 != 0.0f) atomicAdd(&agg[d.z], v2);
        if (v3 != 0.0f) atomicAdd(&agg[d.w], v3);
        i = ni; s = ns; d = nd; valid = nvalid;
    }
}

// Per-node: s1 = agg*dinv ; relu + dropout2 (16 ch) ; dot W2 ; g2 = t*dinv (fp16)
__global__ void k_node2(const float* __restrict__ W1, const float* __restrict__ b1,
                        const float* __restrict__ W2, int N,
                        uint32_t ka, uint32_t kb) {
    int n = blockIdx.x * blockDim.x + threadIdx.x;
    if (n >= N) return;
    float dinv = g_dinv[n];
    float s1 = g_agg[n] * dinv;
    uint32_t base = (uint32_t)n * 16u;
    float t = 0.0f;
#pragma unroll
    for (int c = 0; c < 16; c++) {
        float v = fmaxf(fmaf(s1, __ldg(&W1[c]), __ldg(&b1[c])), 0.0f);
        if (keep_bit(ka, kb, base + (uint32_t)c))
            t = fmaf(v * 2.5f, __ldg(&W2[c]), t);
    }
    g_val[n] = __float2half_rn(t * dinv);
}

__global__ void k_final(float* __restrict__ out, const float* __restrict__ b2, int N) {
    int n = blockIdx.x * blockDim.x + threadIdx.x;
    if (n >= N) return;
    out[n] = out[n] * g_dinv[n] + __ldg(&b2[0]);
}

// ---------------------------------------------------------------------------
// launch
// ---------------------------------------------------------------------------
extern "C" void kernel_launch(void* const* d_in, const int* in_sizes, int n_in,
                              void* d_out, int out_size) {
    const float*     x  = (const float*)d_in[0];
    const long long* ei = (const long long*)d_in[1];
    const float*     W1 = (const float*)d_in[2];
    const float*     b1 = (const float*)d_in[3];
    const float*     W2 = (const float*)d_in[4];
    const float*     b2 = (const float*)d_in[5];
    float* out = (float*)d_out;

    int N = in_sizes[0];
    int E = in_sizes[1] / 2;

    // JAX: key(42)=(0,42); partitionable split: subkey i = threefry(key,(0,i))
    uint32_t k1a, k1b, k2a, k2b;
    tf2x32(0u, 42u, 0u, 0u, k1a, k1b);
    tf2x32(0u, 42u, 0u, 1u, k2a, k2b);

    float* p_agg = nullptr;
    unsigned* p_deg = nullptr;
    cudaGetSymbolAddress((void**)&p_agg, g_agg);
    cudaGetSymbolAddress((void**)&p_deg, g_deg);

    size_t smem_bytes = (((size_t)N * sizeof(__half)) + 15) & ~(size_t)15;
    cudaFuncSetAttribute(k_edge, cudaFuncAttributeMaxDynamicSharedMemorySize,
                         (int)smem_bytes);

    const int T = 256;
    int nb = (N + T - 1) / T;
    int e4 = (E + 3) / 4;

    // zero-init via memset nodes (capturable, overlap with detect)
    cudaMemsetAsync(p_deg, 0, (size_t)N * sizeof(unsigned));
    cudaMemsetAsync(p_agg, 0, (size_t)N * sizeof(float));
    cudaMemsetAsync(out,   0, (size_t)N * sizeof(float));
    k_detect <<<1, 256>>>((const unsigned*)ei);
    k_convert<<<3200, T>>>(ei, E);
    k_node1  <<<nb, T>>>(x, N, k1a, k1b);
    k_edge   <<<148, 1024, smem_bytes>>>(p_agg, e4, N);
    k_node2  <<<nb, T>>>(W1, b1, W2, N, k2a, k2b);
    k_edge   <<<148, 1024, smem_bytes>>>(out, e4, N);
    k_final  <<<nb, T>>>(out, b2, N);
}

// round 13
// speedup vs baseline: 1.0149x; 1.0149x over previous
#include <cuda_runtime.h>
#include <cuda_fp16.h>
#include <stdint.h>

#define N_MAX 100000
#define E_MAX 6400000

// ---- scratch (device globals: no allocation allowed) ----
__device__ int      g_src[E_MAX];
__device__ int      g_dst[E_MAX];
__device__ unsigned g_deg[N_MAX];
__device__ float    g_dinv[N_MAX];
__device__ __half   g_val[N_MAX];   // per-node payload (fp16, 195KB)
__device__ float    g_agg[N_MAX];   // layer-1 aggregation (fp32 atomics)
__device__ int      g_is64;         // edge_index dtype flag (1 = int64)

// ---------------------------------------------------------------------------
// threefry2x32 — exact JAX schedule: 20 rounds = 5 blocks of 4
// ---------------------------------------------------------------------------
__host__ __device__ __forceinline__ void tf2x32(uint32_t k0, uint32_t k1,
                                                uint32_t x0, uint32_t x1,
                                                uint32_t &o0, uint32_t &o1) {
    const uint32_t ks2 = k0 ^ k1 ^ 0x1BD11BDAu;
#define TF_RND(R) { x0 += x1; x1 = (x1 << (R)) | (x1 >> (32 - (R))); x1 ^= x0; }
    x0 += k0; x1 += k1;
    TF_RND(13) TF_RND(15) TF_RND(26) TF_RND(6)
    x0 += k1;  x1 += ks2 + 1u;
    TF_RND(17) TF_RND(29) TF_RND(16) TF_RND(24)
    x0 += ks2; x1 += k0 + 2u;
    TF_RND(13) TF_RND(15) TF_RND(26) TF_RND(6)
    x0 += k0;  x1 += k1 + 3u;
    TF_RND(17) TF_RND(29) TF_RND(16) TF_RND(24)
    x0 += k1;  x1 += ks2 + 4u;
    TF_RND(13) TF_RND(15) TF_RND(26) TF_RND(6)
    x0 += ks2; x1 += k0 + 5u;
#undef TF_RND
    o0 = x0; o1 = x1;
}

__device__ __forceinline__ bool keep_bit(uint32_t ka, uint32_t kb, uint32_t idx) {
    uint32_t a, b;
    tf2x32(ka, kb, 0u, idx, a, b);
    uint32_t bits = a ^ b;
    float u = __uint_as_float((bits >> 9) | 0x3f800000u) - 1.0f;
    return u < 0.4f;
}

// ---------------------------------------------------------------------------
// kernels
// ---------------------------------------------------------------------------

// dtype detection only (zeroing done by cudaMemsetAsync nodes)
__global__ void k_detect(const unsigned* __restrict__ e) {
    __shared__ int any32;
    if (threadIdx.x == 0) any32 = 0;
    __syncthreads();
    int local = 0;
    for (int j = threadIdx.x; j < 4096; j += blockDim.x)
        if (e[2 * j + 1] != 0u) local = 1;
    if (local) any32 = 1;
    __syncthreads();
    if (threadIdx.x == 0) g_is64 = (any32 == 0) ? 1 : 0;
}

// Convert edge_index -> int32 src/dst and count in-degree. 4 edges per thread
// (R9 configuration: exact grid, no grid-stride, no tail branch divergence).
__global__ void __launch_bounds__(256) k_convert(const long long* __restrict__ e, int E) {
    int i = blockIdx.x * blockDim.x + threadIdx.x;   // quad index
    if (i * 4 >= E) return;
    int4 sv, dv;
    if (g_is64) {
        const longlong2* s2 = reinterpret_cast<const longlong2*>(e);
        const longlong2* d2 = reinterpret_cast<const longlong2*>(e + E);
        longlong2 sa = s2[2 * i], sb = s2[2 * i + 1];
        longlong2 da = d2[2 * i], db = d2[2 * i + 1];
        sv = make_int4((int)sa.x, (int)sa.y, (int)sb.x, (int)sb.y);
        dv = make_int4((int)da.x, (int)da.y, (int)db.x, (int)db.y);
    } else {
        const int* e32 = reinterpret_cast<const int*>(e);
        sv = reinterpret_cast<const int4*>(e32)[i];
        dv = reinterpret_cast<const int4*>(e32 + E)[i];
    }
    reinterpret_cast<int4*>(g_src)[i] = sv;
    reinterpret_cast<int4*>(g_dst)[i] = dv;
    atomicAdd(&g_deg[dv.x], 1u);
    atomicAdd(&g_deg[dv.y], 1u);
    atomicAdd(&g_deg[dv.z], 1u);
    atomicAdd(&g_deg[dv.w], 1u);
}

// Per-node: dinv, dropout1 on x, g1 = h1 * dinv  (stored fp16)
__global__ void k_node1(const float* __restrict__ x, int N, uint32_t ka, uint32_t kb) {
    int n = blockIdx.x * blockDim.x + threadIdx.x;
    if (n >= N) return;
    unsigned dg = g_deg[n];
    float dinv = dg ? rsqrtf((float)dg) : 0.0f;
    g_dinv[n] = dinv;
    float h = keep_bit(ka, kb, (uint32_t)n) ? x[n] * 2.5f : 0.0f;
    g_val[n] = __float2half_rn(h * dinv);
}

// Edge scatter: agg[dst] += val[src], skipping zero contributions
// (dropout makes ~60% of pass-1 values exactly zero -> no atomic needed).
// fp16 node table staged in SMEM; index loads (streaming) software-pipelined.
__global__ void __launch_bounds__(1024, 1) k_edge(float* __restrict__ agg, int n4, int N) {
    extern __shared__ __half s_val[];
    int n_u4 = (N + 7) / 8;   // uint4 = 8 halves
    const uint4* st = reinterpret_cast<const uint4*>(g_val);
    uint4* dt = reinterpret_cast<uint4*>(s_val);
    for (int j = threadIdx.x; j < n_u4; j += blockDim.x)
        dt[j] = st[j];
    __syncthreads();

    const int4* s4 = reinterpret_cast<const int4*>(g_src);
    const int4* d4 = reinterpret_cast<const int4*>(g_dst);
    int stride = gridDim.x * blockDim.x;
    int i = blockIdx.x * blockDim.x + threadIdx.x;

    int4 s, d;
    bool valid = (i < n4);
    if (valid) { s = __ldcs(&s4[i]); d = __ldcs(&d4[i]); }
    while (valid) {
        int ni = i + stride;
        bool nvalid = (ni < n4);
        int4 ns, nd;
        if (nvalid) { ns = __ldcs(&s4[ni]); nd = __ldcs(&d4[ni]); }  // prefetch
        float v0 = __half2float(s_val[s.x]);
        float v1 = __half2float(s_val[s.y]);
        float v2 = __half2float(s_val[s.z]);
        float v3 = __half2float(s_val[s.w]);
        if (v0 != 0.0f) atomicAdd(&agg[d.x], v0);
        if (v1 != 0.0f) atomicAdd(&agg[d.y], v1);
        if (v2 != 0.0f) atomicAdd(&agg[d.z], v2);
        if (v3 != 0.0f) atomicAdd(&agg[d.w], v3);
        i = ni; s = ns; d = nd; valid = nvalid;
    }
}

// Per-node: s1 = agg*dinv ; relu + dropout2 (16 ch) ; dot W2 ; g2 = t*dinv (fp16)
__global__ void k_node2(const float* __restrict__ W1, const float* __restrict__ b1,
                        const float* __restrict__ W2, int N,
                        uint32_t ka, uint32_t kb) {
    int n = blockIdx.x * blockDim.x + threadIdx.x;
    if (n >= N) return;
    float dinv = g_dinv[n];
    float s1 = g_agg[n] * dinv;
    uint32_t base = (uint32_t)n * 16u;
    float t = 0.0f;
#pragma unroll
    for (int c = 0; c < 16; c++) {
        float v = fmaxf(fmaf(s1, __ldg(&W1[c]), __ldg(&b1[c])), 0.0f);
        if (keep_bit(ka, kb, base + (uint32_t)c))
            t = fmaf(v * 2.5f, __ldg(&W2[c]), t);
    }
    g_val[n] = __float2half_rn(t * dinv);
}

__global__ void k_final(float* __restrict__ out, const float* __restrict__ b2, int N) {
    int n = blockIdx.x * blockDim.x + threadIdx.x;
    if (n >= N) return;
    out[n] = out[n] * g_dinv[n] + __ldg(&b2[0]);
}

// ---------------------------------------------------------------------------
// launch
// ---------------------------------------------------------------------------
extern "C" void kernel_launch(void* const* d_in, const int* in_sizes, int n_in,
                              void* d_out, int out_size) {
    const float*     x  = (const float*)d_in[0];
    const long long* ei = (const long long*)d_in[1];
    const float*     W1 = (const float*)d_in[2];
    const float*     b1 = (const float*)d_in[3];
    const float*     W2 = (const float*)d_in[4];
    const float*     b2 = (const float*)d_in[5];
    float* out = (float*)d_out;

    int N = in_sizes[0];
    int E = in_sizes[1] / 2;

    // JAX: key(42)=(0,42); partitionable split: subkey i = threefry(key,(0,i))
    uint32_t k1a, k1b, k2a, k2b;
    tf2x32(0u, 42u, 0u, 0u, k1a, k1b);
    tf2x32(0u, 42u, 0u, 1u, k2a, k2b);

    float* p_agg = nullptr;
    unsigned* p_deg = nullptr;
    cudaGetSymbolAddress((void**)&p_agg, g_agg);
    cudaGetSymbolAddress((void**)&p_deg, g_deg);

    size_t smem_bytes = (((size_t)N * sizeof(__half)) + 15) & ~(size_t)15;
    cudaFuncSetAttribute(k_edge, cudaFuncAttributeMaxDynamicSharedMemorySize,
                         (int)smem_bytes);

    const int T = 256;
    int nb = (N + T - 1) / T;
    int e4 = (E + 3) / 4;
    int cb = (e4 + T - 1) / T;

    // zero-init via memset nodes (graph-capturable)
    cudaMemsetAsync(p_deg, 0, (size_t)N * sizeof(unsigned));
    cudaMemsetAsync(p_agg, 0, (size_t)N * sizeof(float));
    cudaMemsetAsync(out,   0, (size_t)N * sizeof(float));
    k_detect <<<1, 256>>>((const unsigned*)ei);
    k_convert<<<cb, T>>>(ei, E);
    k_node1  <<<nb, T>>>(x, N, k1a, k1b);
    k_edge   <<<148, 1024, smem_bytes>>>(p_agg, e4, N);
    k_node2  <<<nb, T>>>(W1, b1, W2, N, k2a, k2b);
    k_edge   <<<148, 1024, smem_bytes>>>(out, e4, N);
    k_final  <<<nb, T>>>(out, b2, N);
}

// round 14
// speedup vs baseline: 1.1159x; 1.0996x over previous
#include <cuda_runtime.h>
#include <cuda_fp16.h>
#include <stdint.h>

#define N_MAX 100000
#define E_MAX 6400000

// ---- scratch (device globals: no allocation allowed) ----
__device__ int      g_src[E_MAX];
__device__ int      g_dst[E_MAX];
__device__ unsigned g_deg[N_MAX];
__device__ float    g_dinv[N_MAX];
__device__ __half   g_val[N_MAX];   // per-node payload (fp16, 195KB)
__device__ float    g_agg[N_MAX];   // layer-1 aggregation (fp32 atomics)
__device__ int      g_is64;         // edge_index dtype flag (1 = int64)

// ---------------------------------------------------------------------------
// threefry2x32 — exact JAX schedule: 20 rounds = 5 blocks of 4
// ---------------------------------------------------------------------------
__host__ __device__ __forceinline__ void tf2x32(uint32_t k0, uint32_t k1,
                                                uint32_t x0, uint32_t x1,
                                                uint32_t &o0, uint32_t &o1) {
    const uint32_t ks2 = k0 ^ k1 ^ 0x1BD11BDAu;
#define TF_RND(R) { x0 += x1; x1 = (x1 << (R)) | (x1 >> (32 - (R))); x1 ^= x0; }
    x0 += k0; x1 += k1;
    TF_RND(13) TF_RND(15) TF_RND(26) TF_RND(6)
    x0 += k1;  x1 += ks2 + 1u;
    TF_RND(17) TF_RND(29) TF_RND(16) TF_RND(24)
    x0 += ks2; x1 += k0 + 2u;
    TF_RND(13) TF_RND(15) TF_RND(26) TF_RND(6)
    x0 += k0;  x1 += k1 + 3u;
    TF_RND(17) TF_RND(29) TF_RND(16) TF_RND(24)
    x0 += k1;  x1 += ks2 + 4u;
    TF_RND(13) TF_RND(15) TF_RND(26) TF_RND(6)
    x0 += ks2; x1 += k0 + 5u;
#undef TF_RND
    o0 = x0; o1 = x1;
}

__device__ __forceinline__ bool keep_bit(uint32_t ka, uint32_t kb, uint32_t idx) {
    uint32_t a, b;
    tf2x32(ka, kb, 0u, idx, a, b);
    uint32_t bits = a ^ b;
    float u = __uint_as_float((bits >> 9) | 0x3f800000u) - 1.0f;
    return u < 0.4f;
}

// ---------------------------------------------------------------------------
// kernels
// ---------------------------------------------------------------------------

// zero counters/accumulators/out + dtype detection (block 0) — fused (R9 form)
__global__ void k_init(float* __restrict__ out, const unsigned* __restrict__ e, int N) {
    int n = blockIdx.x * blockDim.x + threadIdx.x;
    if (n < N) { g_deg[n] = 0u; g_agg[n] = 0.0f; out[n] = 0.0f; }
    if (blockIdx.x == 0) {
        __shared__ int any32;
        if (threadIdx.x == 0) any32 = 0;
        __syncthreads();
        int local = 0;
        for (int j = threadIdx.x; j < 4096; j += blockDim.x)
            if (e[2 * j + 1] != 0u) local = 1;
        if (local) any32 = 1;
        __syncthreads();
        if (threadIdx.x == 0) g_is64 = (any32 == 0) ? 1 : 0;
    }
}

// Convert edge_index -> int32 src/dst and count in-degree. 4 edges per thread.
__global__ void __launch_bounds__(256) k_convert(const long long* __restrict__ e, int E) {
    int i = blockIdx.x * blockDim.x + threadIdx.x;   // quad index
    if (i * 4 >= E) return;
    int4 sv, dv;
    if (g_is64) {
        const longlong2* s2 = reinterpret_cast<const longlong2*>(e);
        const longlong2* d2 = reinterpret_cast<const longlong2*>(e + E);
        longlong2 sa = s2[2 * i], sb = s2[2 * i + 1];
        longlong2 da = d2[2 * i], db = d2[2 * i + 1];
        sv = make_int4((int)sa.x, (int)sa.y, (int)sb.x, (int)sb.y);
        dv = make_int4((int)da.x, (int)da.y, (int)db.x, (int)db.y);
    } else {
        const int* e32 = reinterpret_cast<const int*>(e);
        sv = reinterpret_cast<const int4*>(e32)[i];
        dv = reinterpret_cast<const int4*>(e32 + E)[i];
    }
    reinterpret_cast<int4*>(g_src)[i] = sv;
    reinterpret_cast<int4*>(g_dst)[i] = dv;
    atomicAdd(&g_deg[dv.x], 1u);
    atomicAdd(&g_deg[dv.y], 1u);
    atomicAdd(&g_deg[dv.z], 1u);
    atomicAdd(&g_deg[dv.w], 1u);
}

// Per-node: dinv, dropout1 on x, g1 = h1 * dinv  (stored fp16)
__global__ void k_node1(const float* __restrict__ x, int N, uint32_t ka, uint32_t kb) {
    int n = blockIdx.x * blockDim.x + threadIdx.x;
    if (n >= N) return;
    unsigned dg = g_deg[n];
    float dinv = dg ? rsqrtf((float)dg) : 0.0f;
    g_dinv[n] = dinv;
    float h = keep_bit(ka, kb, (uint32_t)n) ? x[n] * 2.5f : 0.0f;
    g_val[n] = __float2half_rn(h * dinv);
}

// Edge scatter: agg[dst] += val[src], skipping zero contributions
// (dropout makes ~60% of pass-1 values exactly zero -> no atomic needed).
// fp16 node table staged in SMEM; streaming index loads software-pipelined.
__global__ void __launch_bounds__(1024, 1) k_edge(float* __restrict__ agg, int n4, int N) {
    extern __shared__ __half s_val[];
    int n_u4 = (N + 7) / 8;   // uint4 = 8 halves
    const uint4* st = reinterpret_cast<const uint4*>(g_val);
    uint4* dt = reinterpret_cast<uint4*>(s_val);
    for (int j = threadIdx.x; j < n_u4; j += blockDim.x)
        dt[j] = st[j];
    __syncthreads();

    const int4* s4 = reinterpret_cast<const int4*>(g_src);
    const int4* d4 = reinterpret_cast<const int4*>(g_dst);
    int stride = gridDim.x * blockDim.x;
    int i = blockIdx.x * blockDim.x + threadIdx.x;

    int4 s, d;
    bool valid = (i < n4);
    if (valid) { s = __ldcs(&s4[i]); d = __ldcs(&d4[i]); }
    while (valid) {
        int ni = i + stride;
        bool nvalid = (ni < n4);
        int4 ns, nd;
        if (nvalid) { ns = __ldcs(&s4[ni]); nd = __ldcs(&d4[ni]); }  // prefetch
        float v0 = __half2float(s_val[s.x]);
        float v1 = __half2float(s_val[s.y]);
        float v2 = __half2float(s_val[s.z]);
        float v3 = __half2float(s_val[s.w]);
        if (v0 != 0.0f) atomicAdd(&agg[d.x], v0);
        if (v1 != 0.0f) atomicAdd(&agg[d.y], v1);
        if (v2 != 0.0f) atomicAdd(&agg[d.z], v2);
        if (v3 != 0.0f) atomicAdd(&agg[d.w], v3);
        i = ni; s = ns; d = nd; valid = nvalid;
    }
}

// Per-node: s1 = agg*dinv ; relu + dropout2 (16 ch) ; dot W2 ; g2 = t*dinv (fp16)
__global__ void k_node2(const float* __restrict__ W1, const float* __restrict__ b1,
                        const float* __restrict__ W2, int N,
                        uint32_t ka, uint32_t kb) {
    int n = blockIdx.x * blockDim.x + threadIdx.x;
    if (n >= N) return;
    float dinv = g_dinv[n];
    float s1 = g_agg[n] * dinv;
    uint32_t base = (uint32_t)n * 16u;
    float t = 0.0f;
#pragma unroll
    for (int c = 0; c < 16; c++) {
        float v = fmaxf(fmaf(s1, __ldg(&W1[c]), __ldg(&b1[c])), 0.0f);
        if (keep_bit(ka, kb, base + (uint32_t)c))
            t = fmaf(v * 2.5f, __ldg(&W2[c]), t);
    }
    g_val[n] = __float2half_rn(t * dinv);
}

__global__ void k_final(float* __restrict__ out, const float* __restrict__ b2, int N) {
    int n = blockIdx.x * blockDim.x + threadIdx.x;
    if (n >= N) return;
    out[n] = out[n] * g_dinv[n] + __ldg(&b2[0]);
}

// ---------------------------------------------------------------------------
// launch
// ---------------------------------------------------------------------------
extern "C" void kernel_launch(void* const* d_in, const int* in_sizes, int n_in,
                              void* d_out, int out_size) {
    const float*     x  = (const float*)d_in[0];
    const long long* ei = (const long long*)d_in[1];
    const float*     W1 = (const float*)d_in[2];
    const float*     b1 = (const float*)d_in[3];
    const float*     W2 = (const float*)d_in[4];
    const float*     b2 = (const float*)d_in[5];
    float* out = (float*)d_out;

    int N = in_sizes[0];
    int E = in_sizes[1] / 2;

    // JAX: key(42)=(0,42); partitionable split: subkey i = threefry(key,(0,i))
    uint32_t k1a, k1b, k2a, k2b;
    tf2x32(0u, 42u, 0u, 0u, k1a, k1b);
    tf2x32(0u, 42u, 0u, 1u, k2a, k2b);

    float* p_agg = nullptr;
    cudaGetSymbolAddress((void**)&p_agg, g_agg);

    size_t smem_bytes = (((size_t)N * sizeof(__half)) + 15) & ~(size_t)15;
    cudaFuncSetAttribute(k_edge, cudaFuncAttributeMaxDynamicSharedMemorySize,
                         (int)smem_bytes);

    const int T = 256;
    int nb = (N + T - 1) / T;
    int e4 = (E + 3) / 4;
    int cb = (e4 + T - 1) / T;

    k_init   <<<nb, T>>>(out, (const unsigned*)ei, N);
    k_convert<<<cb, T>>>(ei, E);
    k_node1  <<<nb, T>>>(x, N, k1a, k1b);
    k_edge   <<<148, 1024, smem_bytes>>>(p_agg, e4, N);
    k_node2  <<<nb, T>>>(W1, b1, W2, N, k2a, k2b);
    k_edge   <<<148, 1024, smem_bytes>>>(out, e4, N);
    k_final  <<<nb, T>>>(out, b2, N);
}